// round 9
// baseline (speedup 1.0000x reference)
#include <cuda_runtime.h>
#include <cuda_fp16.h>
#include <cstdint>
#include <math.h>

#define NPTS   65536
#define BATCH  4
#define DM     128
#define MLPW   256
#define NFREQ  10
#define IN0    170
#define MT     64
#define PI_F   3.14159265358979323846f

// A smem: 64 rows x 264 fp16 (stride 528B), hi + lo planes
#define ASTR   528
#define A_HI   0
#define A_LO   33792
// W buffers: 3 x (256 rows x 48B)  (K=16 fp16 = 32B data + 16B pad)
#define WB0    67584
#define WBUF   12288
// params
#define SM_G    104448
#define SM_BETA 105472
#define SM_BIAS 106496
#define SM_WO   110592
#define SMEM_BYTES 113664

#define NTHR   256

__device__ __align__(128) __half g_wh[4*256*256];
__device__ float g_gamma1[BATCH*MLPW];
__device__ float g_beta[BATCH*MLPW];

__device__ __forceinline__ uint32_t smem_u32(const void* p) {
    uint32_t a;
    asm("{ .reg .u64 t; cvta.to.shared.u64 t, %1; cvt.u32.u64 %0, t; }" : "=r"(a) : "l"(p));
    return a;
}
__device__ __forceinline__ void cp16(uint32_t dst, const void* src) {
    asm volatile("cp.async.cg.shared.global [%0], [%1], 16;" :: "r"(dst), "l"(src));
}
#define CP_COMMIT() asm volatile("cp.async.commit_group;" ::: "memory")
template <int N> __device__ __forceinline__ void cp_wait() {
    asm volatile("cp.async.wait_group %0;" :: "n"(N) : "memory");
}
__device__ __forceinline__ void ldsm4(uint32_t* r, uint32_t addr) {
    asm volatile("ldmatrix.sync.aligned.m8n8.x4.shared.b16 {%0,%1,%2,%3}, [%4];"
                 : "=r"(r[0]), "=r"(r[1]), "=r"(r[2]), "=r"(r[3]) : "r"(addr));
}
__device__ __forceinline__ void mma16816(float* c, const uint32_t* a, const uint32_t* b) {
    asm volatile("mma.sync.aligned.m16n8k16.row.col.f32.f16.f16.f32 "
                 "{%0,%1,%2,%3}, {%4,%5,%6,%7}, {%8,%9}, {%0,%1,%2,%3};"
                 : "+f"(c[0]), "+f"(c[1]), "+f"(c[2]), "+f"(c[3])
                 : "r"(a[0]), "r"(a[1]), "r"(a[2]), "r"(a[3]), "r"(b[0]), "r"(b[1]));
}
__device__ __forceinline__ float gelu_fast(float x) {
    float u = 0.7978845608028654f * fmaf(0.044715f * x, x * x, x);
    float e, rc;
    asm("ex2.approx.f32 %0, %1;" : "=f"(e) : "f"(u * 2.8853900817779268f));
    asm("rcp.approx.f32 %0, %1;" : "=f"(rc) : "f"(e + 1.0f));
    return x * (1.0f - rc);
}
// fp16 hi/lo split of a pair (rn both stages; a = hi + lo exact to 2^-22)
__device__ __forceinline__ void split2(float z0, float z1, uint32_t& h, uint32_t& l) {
    __half2 hp = __floats2half2_rn(z0, z1);
    h = *(uint32_t*)&hp;
    float r0 = z0 - __half2float(__low2half(hp));
    float r1 = z1 - __half2float(__high2half(hp));
    __half2 lp = __floats2half2_rn(r0, r1);
    l = *(uint32_t*)&lp;
}

// ---------- prep: transpose W, round to fp16 ----------
__global__ void prep_w_kernel(const float* __restrict__ w0, const float* __restrict__ w1,
                              const float* __restrict__ w2, const float* __restrict__ w3) {
    int l = blockIdx.y, k = blockIdx.x, n = threadIdx.x;
    const float* w = (l == 0) ? w0 : (l == 1) ? w1 : (l == 2) ? w2 : w3;
    int kd = (l == 0) ? IN0 : MLPW;
    float v = (k < kd) ? w[k * MLPW + n] : 0.0f;
    g_wh[((size_t)l * 256 + n) * 256 + k] = __float2half_rn(v);
}

__global__ void film_kernel(const float* __restrict__ ctx,
                            const float* __restrict__ wf,
                            const float* __restrict__ bf) {
    int b = blockIdx.x, j = threadIdx.x;
    float acc = bf[j];
    const float* c = ctx + b * DM;
#pragma unroll 4
    for (int k = 0; k < DM; k++)
        acc = fmaf(__ldg(&c[k]), __ldg(&wf[k * 2 * MLPW + j]), acc);
    if (j < MLPW) g_gamma1[b * MLPW + j] = acc + 1.0f;
    else          g_beta[b * MLPW + (j - MLPW)] = acc;
}

// load W chunk (K=16 slice) for (layer l, local chunk c) into buffer buf (256 thr)
__device__ __forceinline__ void load_chunk(uint32_t base, int buf, int l, int c, int tid) {
    uint32_t d = base + WB0 + buf * WBUF + tid * 48;
    const __half* s = g_wh + ((size_t)l * 256 + tid) * 256 + c * 16;
    cp16(d, s);
    cp16(d + 16, s + 8);
}

// ---------- main kernel ----------
__global__ void __launch_bounds__(NTHR, 2)
decoder_kernel(const float* __restrict__ fgrid, const float* __restrict__ coords,
               const float* __restrict__ b0p, const float* __restrict__ b1p,
               const float* __restrict__ b2p, const float* __restrict__ b3p,
               const float* __restrict__ wo, const float* __restrict__ bo,
               float* __restrict__ out) {
    extern __shared__ char smc[];
    const uint32_t base = smem_u32(smc);
    const int tid  = threadIdx.x;
    const int w    = tid >> 5, lane = tid & 31;
    const int b    = blockIdx.y;
    const int n0g  = blockIdx.x * MT;
    const int nw0  = w * 32;                 // warp N offset (8 warps, all in N)

    // lane-fixed ldmatrix offsets
    const int lg   = lane >> 3, lr = lane & 7;
    const int aRow = lr + ((lg & 1) << 3);
    const int aKh  = (lg >> 1) << 3;
    const int bN   = lr + ((lg >> 1) << 3);
    const int bKh  = (lg & 1) << 3;
    const uint32_t aOffH = base + A_HI + (uint32_t)aRow * ASTR + aKh * 2;
    const uint32_t aOffL = base + A_LO + (uint32_t)aRow * ASTR + aKh * 2;
    const uint32_t bOff  = (uint32_t)(nw0 + bN) * 48 + bKh * 2;

    // prefetch first two W chunks of layer 0
    load_chunk(base, 0, 0, 0, tid); CP_COMMIT();
    load_chunk(base, 1, 0, 1, tid); CP_COMMIT();

    // stage params
    float* shg   = (float*)(smc + SM_G);
    float* shb   = (float*)(smc + SM_BETA);
    float* sbias = (float*)(smc + SM_BIAS);
    float* swo   = (float*)(smc + SM_WO);
    shg[tid] = g_gamma1[b * MLPW + tid];
    shb[tid] = g_beta[b * MLPW + tid];
    sbias[tid]       = __ldg(&b0p[tid]);
    sbias[256 + tid] = __ldg(&b1p[tid]);
    sbias[512 + tid] = __ldg(&b2p[tid]);
    sbias[768 + tid] = __ldg(&b3p[tid]);
    for (int i = tid; i < 768; i += NTHR) swo[i] = __ldg(&wo[i]);

    // ---------- phase A: enc + bilinear sample (vectorized, 4 thr/point) ----------
    {
        int p = tid >> 2, sub = tid & 3;
        int n = n0g + p;
        float cy = __ldg(&coords[2 * n]), cx = __ldg(&coords[2 * n + 1]);
        float py = fminf(fmaxf((cy + 1.0f) * 31.5f, 0.0f), 63.0f);
        float px = fminf(fmaxf((cx + 1.0f) * 31.5f, 0.0f), 63.0f);
        int y0i = min((int)py, 62), x0i = min((int)px, 62);
        float fy = py - (float)y0i, fx = px - (float)x0i;
        float w00 = (1.f - fy) * (1.f - fx), w01 = (1.f - fy) * fx;
        float w10 = fy * (1.f - fx), w11 = fy * fx;
        const float* gb = fgrid + (((size_t)b * 64 + y0i) * 64 + x0i) * DM;
        char* hb = smc + A_HI + p * ASTR;
        char* lb = smc + A_LO + p * ASTR;
#define PUT(j, v) do { float _v = (v); __half _h = __float2half_rn(_v); \
        *(__half*)(hb + 2*(j)) = _h; \
        float _l = _v - __half2float(_h); \
        *(__half*)(lb + 2*(j)) = __float2half_rn(_l); } while(0)
        // 32 channels per thread, float4 loads from 4 corners
        {
            int cs = sub * 32;
            const float4* q00 = (const float4*)gb + (cs >> 2);
            const float4* q01 = (const float4*)(gb + DM) + (cs >> 2);
            const float4* q10 = (const float4*)(gb + 8192) + (cs >> 2);
            const float4* q11 = (const float4*)(gb + 8192 + DM) + (cs >> 2);
#pragma unroll
            for (int q = 0; q < 8; q++) {
                float4 A = __ldg(q00 + q), B = __ldg(q01 + q);
                float4 C = __ldg(q10 + q), D = __ldg(q11 + q);
                int j0 = 42 + cs + 4 * q;
                PUT(j0 + 0, w00*A.x + w01*B.x + w10*C.x + w11*D.x);
                PUT(j0 + 1, w00*A.y + w01*B.y + w10*C.y + w11*D.y);
                PUT(j0 + 2, w00*A.z + w01*B.z + w10*C.z + w11*D.z);
                PUT(j0 + 3, w00*A.w + w01*B.w + w10*C.w + w11*D.w);
            }
        }
        if (sub == 0) {
            PUT(0, cy); PUT(1, cx);
            float sy, cyv, sx, cxv;
            sincosf(PI_F * cy, &sy, &cyv);
            sincosf(PI_F * cx, &sx, &cxv);
#pragma unroll
            for (int i = 0; i < NFREQ; i++) {
                PUT(2 + 4*i + 0, sy);  PUT(2 + 4*i + 1, sx);
                PUT(2 + 4*i + 2, cyv); PUT(2 + 4*i + 3, cxv);
                float ns = 2.f * sy * cyv, nc = 1.f - 2.f * sy * sy;
                sy = ns; cyv = nc;
                ns = 2.f * sx * cxv; nc = 1.f - 2.f * sx * sx;
                sx = ns; cxv = nc;
            }
        } else if (sub == 3) {
            // zero pad cols 170..191 (bytes 340..384, 4B-aligned)
#pragma unroll
            for (int q = 0; q < 11; q++) {
                *(uint32_t*)(hb + 340 + 4*q) = 0u;
                *(uint32_t*)(lb + 340 + 4*q) = 0u;
            }
        }
#undef PUT
    }
    __syncthreads();

    // ---------- mainloop: 60 K=16 chunks over 4 layers, 2 passes each ----------
    float acc[4][4][4];
#pragma unroll
    for (int i = 0; i < 4; i++)
#pragma unroll
        for (int j = 0; j < 4; j++)
#pragma unroll
            for (int r = 0; r < 4; r++) acc[i][j][r] = 0.0f;

    int layer = 0, cloc = 0, nch = 12;
#pragma unroll 1
    for (int g = 0; g < 60; g++) {
        cp_wait<1>();
        __syncthreads();
        // prefetch chunk g+2
        {
            int j = g + 2;
            if (j < 60) {
                int ln = (j < 12) ? 0 : (j - 12) / 16 + 1;
                int cn = (ln == 0) ? j : (j - 12) & 15;
                load_chunk(base, j % 3, ln, cn, tid);
            }
            CP_COMMIT();
        }
        // MMAs for chunk g
        {
            const uint32_t wb = base + WB0 + (uint32_t)(g % 3) * WBUF;
            const uint32_t k2 = (uint32_t)cloc * 32;
            uint32_t af[4][4], bfr[2][4];
#pragma unroll
            for (int j2 = 0; j2 < 2; j2++) ldsm4(bfr[j2], wb + bOff + j2 * 768);
            // pass 1: A_hi x W
#pragma unroll
            for (int i = 0; i < 4; i++) ldsm4(af[i], aOffH + i * (16 * ASTR) + k2);
#pragma unroll
            for (int i = 0; i < 4; i++)
#pragma unroll
                for (int j = 0; j < 4; j++)
                    mma16816(acc[i][j], af[i], &bfr[j >> 1][(j & 1) * 2]);
            // pass 2: A_lo x W (reuse af regs)
#pragma unroll
            for (int i = 0; i < 4; i++) ldsm4(af[i], aOffL + i * (16 * ASTR) + k2);
#pragma unroll
            for (int i = 0; i < 4; i++)
#pragma unroll
                for (int j = 0; j < 4; j++)
                    mma16816(acc[i][j], af[i], &bfr[j >> 1][(j & 1) * 2]);
        }
        cloc++;
        if (cloc == nch) {
            // ---------- layer epilogue ----------
            __syncthreads();   // all warps done reading A for this layer
            const float* bl = sbias + layer * 256;
            const int cb = nw0 + 2 * (lane & 3);
            const int rb = lane >> 2;
#pragma unroll
            for (int j = 0; j < 4; j++) {
                int col = cb + 8 * j;
                float bi0 = bl[col], bi1 = bl[col + 1];
                float gg0 = shg[col], gg1 = shg[col + 1];
                float be0 = shb[col], be1 = shb[col + 1];
#pragma unroll
                for (int i = 0; i < 4; i++) {
                    int row = rb + 16 * i;
                    float z0 = gelu_fast(fmaf(acc[i][j][0] + bi0, gg0, be0));
                    float z1 = gelu_fast(fmaf(acc[i][j][1] + bi1, gg1, be1));
                    float z2 = gelu_fast(fmaf(acc[i][j][2] + bi0, gg0, be0));
                    float z3 = gelu_fast(fmaf(acc[i][j][3] + bi1, gg1, be1));
                    acc[i][j][0] = 0.0f; acc[i][j][1] = 0.0f;
                    acc[i][j][2] = 0.0f; acc[i][j][3] = 0.0f;
                    uint32_t h0, l0, h1, l1;
                    split2(z0, z1, h0, l0);
                    split2(z2, z3, h1, l1);
                    uint32_t o0 = (uint32_t)row * ASTR + (uint32_t)col * 2;
                    uint32_t o1 = o0 + 8 * ASTR;
                    *(uint32_t*)(smc + A_HI + o0) = h0;
                    *(uint32_t*)(smc + A_LO + o0) = l0;
                    *(uint32_t*)(smc + A_HI + o1) = h1;
                    *(uint32_t*)(smc + A_LO + o1) = l1;
                }
            }
            layer++; cloc = 0; nch = 16;
        }
    }
    __syncthreads();

    // ---------- head: 256 -> 3, tanh (reconstruct fp32 from hi+lo) ----------
    if (tid < MT * 3) {
        int pp = tid / 3;
        int j  = tid - pp * 3;
        float a0 = __ldg(&bo[j]);
        const __half* hr = (const __half*)(smc + A_HI + pp * ASTR);
        const __half* lr = (const __half*)(smc + A_LO + pp * ASTR);
#pragma unroll 8
        for (int k = 0; k < 256; k++) {
            float hv = __half2float(hr[k]) + __half2float(lr[k]);
            a0 = fmaf(hv, swo[k * 3 + j], a0);
        }
        out[((size_t)b * NPTS + n0g + pp) * 3 + j] = tanhf(a0);
    }
}

extern "C" void kernel_launch(void* const* d_in, const int* in_sizes, int n_in,
                              void* d_out, int out_size) {
    const float* fgrid  = (const float*)d_in[0];
    const float* ctx    = (const float*)d_in[1];
    const float* coords = (const float*)d_in[2];
    const float* w0 = (const float*)d_in[3];
    const float* b0 = (const float*)d_in[4];
    const float* w1 = (const float*)d_in[5];
    const float* b1 = (const float*)d_in[6];
    const float* w2 = (const float*)d_in[7];
    const float* b2 = (const float*)d_in[8];
    const float* w3 = (const float*)d_in[9];
    const float* b3 = (const float*)d_in[10];
    const float* wf = (const float*)d_in[11];
    const float* bf = (const float*)d_in[12];
    const float* wo = (const float*)d_in[13];
    const float* bo = (const float*)d_in[14];
    float* out = (float*)d_out;

    cudaFuncSetAttribute(decoder_kernel,
                         cudaFuncAttributeMaxDynamicSharedMemorySize, SMEM_BYTES);

    dim3 pgrid(256, 4);
    prep_w_kernel<<<pgrid, 256>>>(w0, w1, w2, w3);
    film_kernel<<<BATCH, 2 * MLPW>>>(ctx, wf, bf);
    dim3 grid(NPTS / MT, BATCH);
    decoder_kernel<<<grid, NTHR, SMEM_BYTES>>>(fgrid, coords, b0, b1, b2, b3,
                                               wo, bo, out);
}

// round 10
// speedup vs baseline: 1.6327x; 1.6327x over previous
#include <cuda_runtime.h>
#include <cuda_fp16.h>
#include <cstdint>
#include <math.h>

#define NPTS   65536
#define BATCH  4
#define DM     128
#define MLPW   256
#define NFREQ  10
#define IN0    170
#define MT     128
#define PI_F   3.14159265358979323846f

// A smem: 128 rows x 264 fp16 (stride 528B), hi + lo planes
#define ASTR   528
#define A_HI   0
#define A_LO   67584
// W buffers: 3 x (256 rows x 80B)  (K=32 fp16 = 64B data + 16B pad)
#define WB0    135168
#define WBUF   20480
// params
#define SM_G    196608
#define SM_BETA 197632
#define SM_BIAS 198656
#define SM_WO   202752
#define SMEM_BYTES 205824

#define NTHR   512

__device__ __align__(128) __half g_wh[4*256*256];
__device__ float g_gamma1[BATCH*MLPW];
__device__ float g_beta[BATCH*MLPW];

__device__ __forceinline__ uint32_t smem_u32(const void* p) {
    uint32_t a;
    asm("{ .reg .u64 t; cvta.to.shared.u64 t, %1; cvt.u32.u64 %0, t; }" : "=r"(a) : "l"(p));
    return a;
}
__device__ __forceinline__ void cp16(uint32_t dst, const void* src) {
    asm volatile("cp.async.cg.shared.global [%0], [%1], 16;" :: "r"(dst), "l"(src));
}
#define CP_COMMIT() asm volatile("cp.async.commit_group;" ::: "memory")
template <int N> __device__ __forceinline__ void cp_wait() {
    asm volatile("cp.async.wait_group %0;" :: "n"(N) : "memory");
}
__device__ __forceinline__ void ldsm4(uint32_t* r, uint32_t addr) {
    asm volatile("ldmatrix.sync.aligned.m8n8.x4.shared.b16 {%0,%1,%2,%3}, [%4];"
                 : "=r"(r[0]), "=r"(r[1]), "=r"(r[2]), "=r"(r[3]) : "r"(addr));
}
__device__ __forceinline__ void mma16816(float* c, const uint32_t* a, const uint32_t* b) {
    asm volatile("mma.sync.aligned.m16n8k16.row.col.f32.f16.f16.f32 "
                 "{%0,%1,%2,%3}, {%4,%5,%6,%7}, {%8,%9}, {%0,%1,%2,%3};"
                 : "+f"(c[0]), "+f"(c[1]), "+f"(c[2]), "+f"(c[3])
                 : "r"(a[0]), "r"(a[1]), "r"(a[2]), "r"(a[3]), "r"(b[0]), "r"(b[1]));
}
__device__ __forceinline__ float gelu_fast(float x) {
    float u = 0.7978845608028654f * fmaf(0.044715f * x, x * x, x);
    float e, rc;
    asm("ex2.approx.f32 %0, %1;" : "=f"(e) : "f"(u * 2.8853900817779268f));
    asm("rcp.approx.f32 %0, %1;" : "=f"(rc) : "f"(e + 1.0f));
    return x * (1.0f - rc);
}
// fp16 hi/lo split of a pair (rn both stages; a = hi + lo exact to 2^-22)
__device__ __forceinline__ void split2(float z0, float z1, uint32_t& h, uint32_t& l) {
    __half2 hp = __floats2half2_rn(z0, z1);
    h = *(uint32_t*)&hp;
    float r0 = z0 - __half2float(__low2half(hp));
    float r1 = z1 - __half2float(__high2half(hp));
    __half2 lp = __floats2half2_rn(r0, r1);
    l = *(uint32_t*)&lp;
}

// ---------- prep: transpose W, round to fp16 ----------
__global__ void prep_w_kernel(const float* __restrict__ w0, const float* __restrict__ w1,
                              const float* __restrict__ w2, const float* __restrict__ w3) {
    int l = blockIdx.y, k = blockIdx.x, n = threadIdx.x;
    const float* w = (l == 0) ? w0 : (l == 1) ? w1 : (l == 2) ? w2 : w3;
    int kd = (l == 0) ? IN0 : MLPW;
    float v = (k < kd) ? w[k * MLPW + n] : 0.0f;
    g_wh[((size_t)l * 256 + n) * 256 + k] = __float2half_rn(v);
}

__global__ void film_kernel(const float* __restrict__ ctx,
                            const float* __restrict__ wf,
                            const float* __restrict__ bf) {
    int b = blockIdx.x, j = threadIdx.x;
    float acc = bf[j];
    const float* c = ctx + b * DM;
#pragma unroll 4
    for (int k = 0; k < DM; k++)
        acc = fmaf(__ldg(&c[k]), __ldg(&wf[k * 2 * MLPW + j]), acc);
    if (j < MLPW) g_gamma1[b * MLPW + j] = acc + 1.0f;
    else          g_beta[b * MLPW + (j - MLPW)] = acc;
}

// load W chunk (K=32 slice) for (layer l, local chunk c) into buffer buf (512 thr)
__device__ __forceinline__ void load_chunk(uint32_t base, int buf, int l, int c, int tid) {
    int row  = tid >> 1;
    int part = tid & 1;          // 32B half of the 64B row
    uint32_t d = base + WB0 + buf * WBUF + row * 80 + part * 32;
    const __half* s = g_wh + ((size_t)l * 256 + row) * 256 + c * 32 + part * 16;
    cp16(d, s);
    cp16(d + 16, s + 8);
}

// ---------- main kernel ----------
__global__ void __launch_bounds__(NTHR, 1)
decoder_kernel(const float* __restrict__ fgrid, const float* __restrict__ coords,
               const float* __restrict__ b0p, const float* __restrict__ b1p,
               const float* __restrict__ b2p, const float* __restrict__ b3p,
               const float* __restrict__ wo, const float* __restrict__ bo,
               float* __restrict__ out) {
    extern __shared__ char smc[];
    const uint32_t base = smem_u32(smc);
    const int tid  = threadIdx.x;
    const int w    = tid >> 5, lane = tid & 31;
    const int b    = blockIdx.y;
    const int n0g  = blockIdx.x * MT;
    const int m0   = (w & 1) * 64;           // warp M offset
    const int nw0  = (w >> 1) * 32;          // warp N offset (16 warps: 2x8)

    // lane-fixed ldmatrix offsets
    const int lg   = lane >> 3, lr = lane & 7;
    const int aRow = lr + ((lg & 1) << 3);
    const int aKh  = (lg >> 1) << 3;
    const int bN   = lr + ((lg >> 1) << 3);
    const int bKh  = (lg & 1) << 3;
    const uint32_t aOffH = base + A_HI + (uint32_t)(m0 + aRow) * ASTR + aKh * 2;
    const uint32_t aOffL = base + A_LO + (uint32_t)(m0 + aRow) * ASTR + aKh * 2;
    const uint32_t bOff  = (uint32_t)(nw0 + bN) * 80 + bKh * 2;

    // prefetch first two W chunks of layer 0
    load_chunk(base, 0, 0, 0, tid); CP_COMMIT();
    load_chunk(base, 1, 0, 1, tid); CP_COMMIT();

    // stage params
    float* shg   = (float*)(smc + SM_G);
    float* shb   = (float*)(smc + SM_BETA);
    float* sbias = (float*)(smc + SM_BIAS);
    float* swo   = (float*)(smc + SM_WO);
    if (tid < 256) {
        shg[tid] = g_gamma1[b * MLPW + tid];
        shb[tid] = g_beta[b * MLPW + tid];
        sbias[tid]       = __ldg(&b0p[tid]);
        sbias[256 + tid] = __ldg(&b1p[tid]);
        sbias[512 + tid] = __ldg(&b2p[tid]);
        sbias[768 + tid] = __ldg(&b3p[tid]);
    }
    for (int i = tid; i < 768; i += NTHR) swo[i] = __ldg(&wo[i]);

    // ---------- phase A: enc + bilinear sample (vectorized, 4 thr/point) ----------
    // Layer 0 consumes only the HI plane (single-pass), so no lo writes here.
    {
        int p = tid >> 2, sub = tid & 3;
        int n = n0g + p;
        float cy = __ldg(&coords[2 * n]), cx = __ldg(&coords[2 * n + 1]);
        float py = fminf(fmaxf((cy + 1.0f) * 31.5f, 0.0f), 63.0f);
        float px = fminf(fmaxf((cx + 1.0f) * 31.5f, 0.0f), 63.0f);
        int y0i = min((int)py, 62), x0i = min((int)px, 62);
        float fy = py - (float)y0i, fx = px - (float)x0i;
        float w00 = (1.f - fy) * (1.f - fx), w01 = (1.f - fy) * fx;
        float w10 = fy * (1.f - fx), w11 = fy * fx;
        const float* gb = fgrid + (((size_t)b * 64 + y0i) * 64 + x0i) * DM;
        char* hb = smc + A_HI + p * ASTR;
#define PUT(j, v) do { *(__half*)(hb + 2*(j)) = __float2half_rn(v); } while(0)
        // 32 channels per thread, float4 loads from 4 corners
        {
            int cs = sub * 32;
            const float4* q00 = (const float4*)gb + (cs >> 2);
            const float4* q01 = (const float4*)(gb + DM) + (cs >> 2);
            const float4* q10 = (const float4*)(gb + 8192) + (cs >> 2);
            const float4* q11 = (const float4*)(gb + 8192 + DM) + (cs >> 2);
#pragma unroll
            for (int q = 0; q < 8; q++) {
                float4 A = __ldg(q00 + q), B = __ldg(q01 + q);
                float4 C = __ldg(q10 + q), D = __ldg(q11 + q);
                int j0 = 42 + cs + 4 * q;
                PUT(j0 + 0, w00*A.x + w01*B.x + w10*C.x + w11*D.x);
                PUT(j0 + 1, w00*A.y + w01*B.y + w10*C.y + w11*D.y);
                PUT(j0 + 2, w00*A.z + w01*B.z + w10*C.z + w11*D.z);
                PUT(j0 + 3, w00*A.w + w01*B.w + w10*C.w + w11*D.w);
            }
        }
        if (sub == 0) {
            PUT(0, cy); PUT(1, cx);
            float sy, cyv, sx, cxv;
            sincosf(PI_F * cy, &sy, &cyv);
            sincosf(PI_F * cx, &sx, &cxv);
#pragma unroll
            for (int i = 0; i < NFREQ; i++) {
                PUT(2 + 4*i + 0, sy);  PUT(2 + 4*i + 1, sx);
                PUT(2 + 4*i + 2, cyv); PUT(2 + 4*i + 3, cxv);
                float ns = 2.f * sy * cyv, nc = 1.f - 2.f * sy * sy;
                sy = ns; cyv = nc;
                ns = 2.f * sx * cxv; nc = 1.f - 2.f * sx * sx;
                sx = ns; cxv = nc;
            }
        } else if (sub == 3) {
            // zero pad cols 170..191 (bytes 340..384, 4B-aligned), hi plane only
#pragma unroll
            for (int q = 0; q < 11; q++)
                *(uint32_t*)(hb + 340 + 4*q) = 0u;
        }
#undef PUT
    }
    __syncthreads();

    // ---------- mainloop: 30 K=32 chunks over 4 layers ----------
    // layer 0 (chunks 0..5): single pass (A_hi only); layers 1-3: 2 passes.
    float acc[4][4][4];
#pragma unroll
    for (int i = 0; i < 4; i++)
#pragma unroll
        for (int j = 0; j < 4; j++)
#pragma unroll
            for (int r = 0; r < 4; r++) acc[i][j][r] = 0.0f;

    int layer = 0, cloc = 0, nch = 6;
#pragma unroll 1
    for (int g = 0; g < 30; g++) {
        cp_wait<1>();
        __syncthreads();
        // prefetch chunk g+2
        {
            int j = g + 2;
            if (j < 30) {
                int ln = (j < 6) ? 0 : (j - 6) / 8 + 1;
                int cn = (ln == 0) ? j : (j - 6) & 7;
                load_chunk(base, j % 3, ln, cn, tid);
            }
            CP_COMMIT();
        }
        // MMAs for chunk g (K=32: two k-subtiles of 16)
        {
            const uint32_t wb = base + WB0 + (uint32_t)(g % 3) * WBUF;
            const uint32_t k2 = (uint32_t)cloc * 64;
            const bool two_pass = (g >= 6);
            uint32_t af[4][4], bfr[2][4];
#pragma unroll
            for (int ks = 0; ks < 2; ks++) {
                const uint32_t kb = k2 + (uint32_t)ks * 32;
#pragma unroll
                for (int j2 = 0; j2 < 2; j2++)
                    ldsm4(bfr[j2], wb + bOff + (uint32_t)ks * 32 + j2 * 1280);
                // pass 1: A_hi x W
#pragma unroll
                for (int i = 0; i < 4; i++) ldsm4(af[i], aOffH + i * (16 * ASTR) + kb);
#pragma unroll
                for (int i = 0; i < 4; i++)
#pragma unroll
                    for (int j = 0; j < 4; j++)
                        mma16816(acc[i][j], af[i], &bfr[j >> 1][(j & 1) * 2]);
                // pass 2: A_lo x W (layers 1-3 only; reuse af regs)
                if (two_pass) {
#pragma unroll
                    for (int i = 0; i < 4; i++) ldsm4(af[i], aOffL + i * (16 * ASTR) + kb);
#pragma unroll
                    for (int i = 0; i < 4; i++)
#pragma unroll
                        for (int j = 0; j < 4; j++)
                            mma16816(acc[i][j], af[i], &bfr[j >> 1][(j & 1) * 2]);
                }
            }
        }
        cloc++;
        if (cloc == nch) {
            // ---------- layer epilogue ----------
            __syncthreads();   // all warps done reading A for this layer
            const float* bl = sbias + layer * 256;
            const int cb = nw0 + 2 * (lane & 3);
            const int rb = m0 + (lane >> 2);
#pragma unroll
            for (int j = 0; j < 4; j++) {
                int col = cb + 8 * j;
                float bi0 = bl[col], bi1 = bl[col + 1];
                float gg0 = shg[col], gg1 = shg[col + 1];
                float be0 = shb[col], be1 = shb[col + 1];
#pragma unroll
                for (int i = 0; i < 4; i++) {
                    int row = rb + 16 * i;
                    float z0 = gelu_fast(fmaf(acc[i][j][0] + bi0, gg0, be0));
                    float z1 = gelu_fast(fmaf(acc[i][j][1] + bi1, gg1, be1));
                    float z2 = gelu_fast(fmaf(acc[i][j][2] + bi0, gg0, be0));
                    float z3 = gelu_fast(fmaf(acc[i][j][3] + bi1, gg1, be1));
                    acc[i][j][0] = 0.0f; acc[i][j][1] = 0.0f;
                    acc[i][j][2] = 0.0f; acc[i][j][3] = 0.0f;
                    uint32_t h0, l0, h1, l1;
                    split2(z0, z1, h0, l0);
                    split2(z2, z3, h1, l1);
                    uint32_t o0 = (uint32_t)row * ASTR + (uint32_t)col * 2;
                    uint32_t o1 = o0 + 8 * ASTR;
                    *(uint32_t*)(smc + A_HI + o0) = h0;
                    *(uint32_t*)(smc + A_LO + o0) = l0;
                    *(uint32_t*)(smc + A_HI + o1) = h1;
                    *(uint32_t*)(smc + A_LO + o1) = l1;
                }
            }
            layer++; cloc = 0; nch = 8;
        }
    }
    __syncthreads();

    // ---------- head: 256 -> 3, tanh (384 threads, 1 output each) ----------
    if (tid < MT * 3) {
        int pp = tid / 3;
        int j  = tid - pp * 3;
        float a0 = __ldg(&bo[j]);
        const __half* hr = (const __half*)(smc + A_HI + pp * ASTR);
        const __half* lr = (const __half*)(smc + A_LO + pp * ASTR);
#pragma unroll 8
        for (int k = 0; k < 256; k++) {
            float hv = __half2float(hr[k]) + __half2float(lr[k]);
            a0 = fmaf(hv, swo[k * 3 + j], a0);
        }
        out[((size_t)b * NPTS + n0g + pp) * 3 + j] = tanhf(a0);
    }
}

extern "C" void kernel_launch(void* const* d_in, const int* in_sizes, int n_in,
                              void* d_out, int out_size) {
    const float* fgrid  = (const float*)d_in[0];
    const float* ctx    = (const float*)d_in[1];
    const float* coords = (const float*)d_in[2];
    const float* w0 = (const float*)d_in[3];
    const float* b0 = (const float*)d_in[4];
    const float* w1 = (const float*)d_in[5];
    const float* b1 = (const float*)d_in[6];
    const float* w2 = (const float*)d_in[7];
    const float* b2 = (const float*)d_in[8];
    const float* w3 = (const float*)d_in[9];
    const float* b3 = (const float*)d_in[10];
    const float* wf = (const float*)d_in[11];
    const float* bf = (const float*)d_in[12];
    const float* wo = (const float*)d_in[13];
    const float* bo = (const float*)d_in[14];
    float* out = (float*)d_out;

    cudaFuncSetAttribute(decoder_kernel,
                         cudaFuncAttributeMaxDynamicSharedMemorySize, SMEM_BYTES);

    dim3 pgrid(256, 4);
    prep_w_kernel<<<pgrid, 256>>>(w0, w1, w2, w3);
    film_kernel<<<BATCH, 2 * MLPW>>>(ctx, wf, bf);
    dim3 grid(NPTS / MT, BATCH);
    decoder_kernel<<<grid, NTHR, SMEM_BYTES>>>(fgrid, coords, b0, b1, b2, b3,
                                               wo, bo, out);
}

// round 11
// speedup vs baseline: 1.9124x; 1.1714x over previous
#include <cuda_runtime.h>
#include <cuda_fp16.h>
#include <cstdint>
#include <math.h>

#define NPTS   65536
#define BATCH  4
#define DM     128
#define MLPW   256
#define NFREQ  10
#define IN0    170
#define MT     128
#define PI_F   3.14159265358979323846f

// A smem: 128 rows x 264 fp16 (stride 528B), hi plane + lo plane (lo: head only)
#define ASTR   528
#define A_HI   0
#define A_LO   67584
// W buffers: 3 x (256 rows x 80B)  (K=32 fp16 = 64B data + 16B pad)
#define WB0    135168
#define WBUF   20480
// params
#define SM_G    196608
#define SM_BETA 197632
#define SM_BIAS 198656
#define SM_WO   202752
#define SMEM_BYTES 205824

#define NTHR   512

__device__ __align__(128) __half g_wh[4*256*256];
__device__ float g_gamma1[BATCH*MLPW];
__device__ float g_beta[BATCH*MLPW];

__device__ __forceinline__ uint32_t smem_u32(const void* p) {
    uint32_t a;
    asm("{ .reg .u64 t; cvta.to.shared.u64 t, %1; cvt.u32.u64 %0, t; }" : "=r"(a) : "l"(p));
    return a;
}
__device__ __forceinline__ void cp16(uint32_t dst, const void* src) {
    asm volatile("cp.async.cg.shared.global [%0], [%1], 16;" :: "r"(dst), "l"(src));
}
#define CP_COMMIT() asm volatile("cp.async.commit_group;" ::: "memory")
template <int N> __device__ __forceinline__ void cp_wait() {
    asm volatile("cp.async.wait_group %0;" :: "n"(N) : "memory");
}
__device__ __forceinline__ void ldsm4(uint32_t* r, uint32_t addr) {
    asm volatile("ldmatrix.sync.aligned.m8n8.x4.shared.b16 {%0,%1,%2,%3}, [%4];"
                 : "=r"(r[0]), "=r"(r[1]), "=r"(r[2]), "=r"(r[3]) : "r"(addr));
}
__device__ __forceinline__ void mma16816(float* c, const uint32_t* a, const uint32_t* b) {
    asm volatile("mma.sync.aligned.m16n8k16.row.col.f32.f16.f16.f32 "
                 "{%0,%1,%2,%3}, {%4,%5,%6,%7}, {%8,%9}, {%0,%1,%2,%3};"
                 : "+f"(c[0]), "+f"(c[1]), "+f"(c[2]), "+f"(c[3])
                 : "r"(a[0]), "r"(a[1]), "r"(a[2]), "r"(a[3]), "r"(b[0]), "r"(b[1]));
}
__device__ __forceinline__ float gelu_fast(float x) {
    float u = 0.7978845608028654f * fmaf(0.044715f * x, x * x, x);
    float e, rc;
    asm("ex2.approx.f32 %0, %1;" : "=f"(e) : "f"(u * 2.8853900817779268f));
    asm("rcp.approx.f32 %0, %1;" : "=f"(rc) : "f"(e + 1.0f));
    return x * (1.0f - rc);
}
// fp16 hi/lo split of a pair (rn both stages; a = hi + lo exact to 2^-22)
__device__ __forceinline__ void split2(float z0, float z1, uint32_t& h, uint32_t& l) {
    __half2 hp = __floats2half2_rn(z0, z1);
    h = *(uint32_t*)&hp;
    float r0 = z0 - __half2float(__low2half(hp));
    float r1 = z1 - __half2float(__high2half(hp));
    __half2 lp = __floats2half2_rn(r0, r1);
    l = *(uint32_t*)&lp;
}

// ---------- prep: transpose W, round to fp16 ----------
__global__ void prep_w_kernel(const float* __restrict__ w0, const float* __restrict__ w1,
                              const float* __restrict__ w2, const float* __restrict__ w3) {
    int l = blockIdx.y, k = blockIdx.x, n = threadIdx.x;
    const float* w = (l == 0) ? w0 : (l == 1) ? w1 : (l == 2) ? w2 : w3;
    int kd = (l == 0) ? IN0 : MLPW;
    float v = (k < kd) ? w[k * MLPW + n] : 0.0f;
    g_wh[((size_t)l * 256 + n) * 256 + k] = __float2half_rn(v);
}

__global__ void film_kernel(const float* __restrict__ ctx,
                            const float* __restrict__ wf,
                            const float* __restrict__ bf) {
    int b = blockIdx.x, j = threadIdx.x;
    float acc = bf[j];
    const float* c = ctx + b * DM;
#pragma unroll 4
    for (int k = 0; k < DM; k++)
        acc = fmaf(__ldg(&c[k]), __ldg(&wf[k * 2 * MLPW + j]), acc);
    if (j < MLPW) g_gamma1[b * MLPW + j] = acc + 1.0f;
    else          g_beta[b * MLPW + (j - MLPW)] = acc;
}

// load W chunk (K=32 slice) for (layer l, local chunk c) into buffer buf (512 thr)
__device__ __forceinline__ void load_chunk(uint32_t base, int buf, int l, int c, int tid) {
    int row  = tid >> 1;
    int part = tid & 1;          // 32B half of the 64B row
    uint32_t d = base + WB0 + buf * WBUF + row * 80 + part * 32;
    const __half* s = g_wh + ((size_t)l * 256 + row) * 256 + c * 32 + part * 16;
    cp16(d, s);
    cp16(d + 16, s + 8);
}

// ---------- main kernel ----------
__global__ void __launch_bounds__(NTHR, 1)
decoder_kernel(const float* __restrict__ fgrid, const float* __restrict__ coords,
               const float* __restrict__ b0p, const float* __restrict__ b1p,
               const float* __restrict__ b2p, const float* __restrict__ b3p,
               const float* __restrict__ wo, const float* __restrict__ bo,
               float* __restrict__ out) {
    extern __shared__ char smc[];
    const uint32_t base = smem_u32(smc);
    const int tid  = threadIdx.x;
    const int w    = tid >> 5, lane = tid & 31;
    const int b    = blockIdx.y;
    const int n0g  = blockIdx.x * MT;
    const int m0   = (w & 1) * 64;           // warp M offset
    const int nw0  = (w >> 1) * 32;          // warp N offset (16 warps: 2x8)

    // lane-fixed ldmatrix offsets
    const int lg   = lane >> 3, lr = lane & 7;
    const int aRow = lr + ((lg & 1) << 3);
    const int aKh  = (lg >> 1) << 3;
    const int bN   = lr + ((lg >> 1) << 3);
    const int bKh  = (lg & 1) << 3;
    const uint32_t aOffH = base + A_HI + (uint32_t)(m0 + aRow) * ASTR + aKh * 2;
    const uint32_t bOff  = (uint32_t)(nw0 + bN) * 80 + bKh * 2;

    // prefetch first two W chunks of layer 0
    load_chunk(base, 0, 0, 0, tid); CP_COMMIT();
    load_chunk(base, 1, 0, 1, tid); CP_COMMIT();

    // stage params
    float* shg   = (float*)(smc + SM_G);
    float* shb   = (float*)(smc + SM_BETA);
    float* sbias = (float*)(smc + SM_BIAS);
    float* swo   = (float*)(smc + SM_WO);
    if (tid < 256) {
        shg[tid] = g_gamma1[b * MLPW + tid];
        shb[tid] = g_beta[b * MLPW + tid];
        sbias[tid]       = __ldg(&b0p[tid]);
        sbias[256 + tid] = __ldg(&b1p[tid]);
        sbias[512 + tid] = __ldg(&b2p[tid]);
        sbias[768 + tid] = __ldg(&b3p[tid]);
    }
    for (int i = tid; i < 768; i += NTHR) swo[i] = __ldg(&wo[i]);

    // ---------- phase A: enc + bilinear sample (vectorized, 4 thr/point) ----------
    // All layers consume only the HI plane; no lo writes here.
    {
        int p = tid >> 2, sub = tid & 3;
        int n = n0g + p;
        float cy = __ldg(&coords[2 * n]), cx = __ldg(&coords[2 * n + 1]);
        float py = fminf(fmaxf((cy + 1.0f) * 31.5f, 0.0f), 63.0f);
        float px = fminf(fmaxf((cx + 1.0f) * 31.5f, 0.0f), 63.0f);
        int y0i = min((int)py, 62), x0i = min((int)px, 62);
        float fy = py - (float)y0i, fx = px - (float)x0i;
        float w00 = (1.f - fy) * (1.f - fx), w01 = (1.f - fy) * fx;
        float w10 = fy * (1.f - fx), w11 = fy * fx;
        const float* gb = fgrid + (((size_t)b * 64 + y0i) * 64 + x0i) * DM;
        char* hb = smc + A_HI + p * ASTR;
#define PUT(j, v) do { *(__half*)(hb + 2*(j)) = __float2half_rn(v); } while(0)
        // 32 channels per thread, float4 loads from 4 corners
        {
            int cs = sub * 32;
            const float4* q00 = (const float4*)gb + (cs >> 2);
            const float4* q01 = (const float4*)(gb + DM) + (cs >> 2);
            const float4* q10 = (const float4*)(gb + 8192) + (cs >> 2);
            const float4* q11 = (const float4*)(gb + 8192 + DM) + (cs >> 2);
#pragma unroll
            for (int q = 0; q < 8; q++) {
                float4 A = __ldg(q00 + q), B = __ldg(q01 + q);
                float4 C = __ldg(q10 + q), D = __ldg(q11 + q);
                int j0 = 42 + cs + 4 * q;
                PUT(j0 + 0, w00*A.x + w01*B.x + w10*C.x + w11*D.x);
                PUT(j0 + 1, w00*A.y + w01*B.y + w10*C.y + w11*D.y);
                PUT(j0 + 2, w00*A.z + w01*B.z + w10*C.z + w11*D.z);
                PUT(j0 + 3, w00*A.w + w01*B.w + w10*C.w + w11*D.w);
            }
        }
        if (sub == 0) {
            PUT(0, cy); PUT(1, cx);
            float sy, cyv, sx, cxv;
            sincosf(PI_F * cy, &sy, &cyv);
            sincosf(PI_F * cx, &sx, &cxv);
#pragma unroll
            for (int i = 0; i < NFREQ; i++) {
                PUT(2 + 4*i + 0, sy);  PUT(2 + 4*i + 1, sx);
                PUT(2 + 4*i + 2, cyv); PUT(2 + 4*i + 3, cxv);
                float ns = 2.f * sy * cyv, nc = 1.f - 2.f * sy * sy;
                sy = ns; cyv = nc;
                ns = 2.f * sx * cxv; nc = 1.f - 2.f * sx * sx;
                sx = ns; cxv = nc;
            }
        } else if (sub == 3) {
            // zero pad cols 170..191 (bytes 340..384, 4B-aligned), hi plane
#pragma unroll
            for (int q = 0; q < 11; q++)
                *(uint32_t*)(hb + 340 + 4*q) = 0u;
        }
#undef PUT
    }
    __syncthreads();

    // ---------- mainloop: 30 K=32 chunks over 4 layers, single pass ----------
    float acc[4][4][4];
#pragma unroll
    for (int i = 0; i < 4; i++)
#pragma unroll
        for (int j = 0; j < 4; j++)
#pragma unroll
            for (int r = 0; r < 4; r++) acc[i][j][r] = 0.0f;

    int layer = 0, cloc = 0, nch = 6;
#pragma unroll 1
    for (int g = 0; g < 30; g++) {
        cp_wait<1>();
        __syncthreads();
        // prefetch chunk g+2
        {
            int j = g + 2;
            if (j < 30) {
                int ln = (j < 6) ? 0 : (j - 6) / 8 + 1;
                int cn = (ln == 0) ? j : (j - 6) & 7;
                load_chunk(base, j % 3, ln, cn, tid);
            }
            CP_COMMIT();
        }
        // MMAs for chunk g (K=32: two k-subtiles of 16)
        {
            const uint32_t wb = base + WB0 + (uint32_t)(g % 3) * WBUF;
            const uint32_t k2 = (uint32_t)cloc * 64;
            uint32_t af[4][4], bfr[2][4];
#pragma unroll
            for (int ks = 0; ks < 2; ks++) {
                const uint32_t kb = k2 + (uint32_t)ks * 32;
#pragma unroll
                for (int j2 = 0; j2 < 2; j2++)
                    ldsm4(bfr[j2], wb + bOff + (uint32_t)ks * 32 + j2 * 1280);
#pragma unroll
                for (int i = 0; i < 4; i++) ldsm4(af[i], aOffH + i * (16 * ASTR) + kb);
#pragma unroll
                for (int i = 0; i < 4; i++)
#pragma unroll
                    for (int j = 0; j < 4; j++)
                        mma16816(acc[i][j], af[i], &bfr[j >> 1][(j & 1) * 2]);
            }
        }
        cloc++;
        if (cloc == nch) {
            // ---------- layer epilogue ----------
            __syncthreads();   // all warps done reading A for this layer
            const float* bl = sbias + layer * 256;
            const int cb = nw0 + 2 * (lane & 3);
            const int rb = m0 + (lane >> 2);
            const bool last = (layer == 3);
#pragma unroll
            for (int j = 0; j < 4; j++) {
                int col = cb + 8 * j;
                float bi0 = bl[col], bi1 = bl[col + 1];
                float gg0 = shg[col], gg1 = shg[col + 1];
                float be0 = shb[col], be1 = shb[col + 1];
#pragma unroll
                for (int i = 0; i < 4; i++) {
                    int row = rb + 16 * i;
                    float z0 = gelu_fast(fmaf(acc[i][j][0] + bi0, gg0, be0));
                    float z1 = gelu_fast(fmaf(acc[i][j][1] + bi1, gg1, be1));
                    float z2 = gelu_fast(fmaf(acc[i][j][2] + bi0, gg0, be0));
                    float z3 = gelu_fast(fmaf(acc[i][j][3] + bi1, gg1, be1));
                    acc[i][j][0] = 0.0f; acc[i][j][1] = 0.0f;
                    acc[i][j][2] = 0.0f; acc[i][j][3] = 0.0f;
                    uint32_t o0 = (uint32_t)row * ASTR + (uint32_t)col * 2;
                    uint32_t o1 = o0 + 8 * ASTR;
                    if (!last) {
                        __half2 h0 = __floats2half2_rn(z0, z1);
                        __half2 h1 = __floats2half2_rn(z2, z3);
                        *(uint32_t*)(smc + A_HI + o0) = *(uint32_t*)&h0;
                        *(uint32_t*)(smc + A_HI + o1) = *(uint32_t*)&h1;
                    } else {
                        // final layer: keep hi+lo so the head sees fp32-accurate input
                        uint32_t h0, l0, h1, l1;
                        split2(z0, z1, h0, l0);
                        split2(z2, z3, h1, l1);
                        *(uint32_t*)(smc + A_HI + o0) = h0;
                        *(uint32_t*)(smc + A_LO + o0) = l0;
                        *(uint32_t*)(smc + A_HI + o1) = h1;
                        *(uint32_t*)(smc + A_LO + o1) = l1;
                    }
                }
            }
            layer++; cloc = 0; nch = 8;
        }
    }
    __syncthreads();

    // ---------- head: 256 -> 3, tanh (384 threads, 1 output each) ----------
    if (tid < MT * 3) {
        int pp = tid / 3;
        int j  = tid - pp * 3;
        float a0 = __ldg(&bo[j]);
        const __half* hr = (const __half*)(smc + A_HI + pp * ASTR);
        const __half* lr = (const __half*)(smc + A_LO + pp * ASTR);
#pragma unroll 8
        for (int k = 0; k < 256; k++) {
            float hv = __half2float(hr[k]) + __half2float(lr[k]);
            a0 = fmaf(hv, swo[k * 3 + j], a0);
        }
        out[((size_t)b * NPTS + n0g + pp) * 3 + j] = tanhf(a0);
    }
}

extern "C" void kernel_launch(void* const* d_in, const int* in_sizes, int n_in,
                              void* d_out, int out_size) {
    const float* fgrid  = (const float*)d_in[0];
    const float* ctx    = (const float*)d_in[1];
    const float* coords = (const float*)d_in[2];
    const float* w0 = (const float*)d_in[3];
    const float* b0 = (const float*)d_in[4];
    const float* w1 = (const float*)d_in[5];
    const float* b1 = (const float*)d_in[6];
    const float* w2 = (const float*)d_in[7];
    const float* b2 = (const float*)d_in[8];
    const float* w3 = (const float*)d_in[9];
    const float* b3 = (const float*)d_in[10];
    const float* wf = (const float*)d_in[11];
    const float* bf = (const float*)d_in[12];
    const float* wo = (const float*)d_in[13];
    const float* bo = (const float*)d_in[14];
    float* out = (float*)d_out;

    cudaFuncSetAttribute(decoder_kernel,
                         cudaFuncAttributeMaxDynamicSharedMemorySize, SMEM_BYTES);

    dim3 pgrid(256, 4);
    prep_w_kernel<<<pgrid, 256>>>(w0, w1, w2, w3);
    film_kernel<<<BATCH, 2 * MLPW>>>(ctx, wf, bf);
    dim3 grid(NPTS / MT, BATCH);
    decoder_kernel<<<grid, NTHR, SMEM_BYTES>>>(fgrid, coords, b0, b1, b2, b3,
                                               wo, bo, out);
}

// round 12
// speedup vs baseline: 2.2812x; 1.1928x over previous
#include <cuda_runtime.h>
#include <cuda_fp16.h>
#include <cstdint>
#include <math.h>

#define NPTS   65536
#define BATCH  4
#define DM     128
#define MLPW   256
#define NFREQ  10
#define IN0    170
#define MT     128
#define PI_F   3.14159265358979323846f

// A smem: 128 rows x 264 fp16 (stride 528B), hi plane only
#define ASTR   528
#define A_HI   0
// W buffers: 3 x (256 rows x 80B)  (K=32 fp16 = 64B data + 16B pad)
#define WB0    67584
#define WBUF   20480
// params
#define SM_G    129024
#define SM_BETA 130048
#define SM_BIAS 131072
#define SM_WO   135168      // w_out fp16, 8 n-rows x 256 k, stride 528B
#define SMEM_BYTES 139392

#define NTHR   512

__device__ __align__(128) __half g_wh[4*256*256];
__device__ float g_gamma1[BATCH*MLPW];
__device__ float g_beta[BATCH*MLPW];

__device__ __forceinline__ uint32_t smem_u32(const void* p) {
    uint32_t a;
    asm("{ .reg .u64 t; cvta.to.shared.u64 t, %1; cvt.u32.u64 %0, t; }" : "=r"(a) : "l"(p));
    return a;
}
__device__ __forceinline__ void cp16(uint32_t dst, const void* src) {
    asm volatile("cp.async.cg.shared.global [%0], [%1], 16;" :: "r"(dst), "l"(src));
}
#define CP_COMMIT() asm volatile("cp.async.commit_group;" ::: "memory")
template <int N> __device__ __forceinline__ void cp_wait() {
    asm volatile("cp.async.wait_group %0;" :: "n"(N) : "memory");
}
__device__ __forceinline__ void ldsm4(uint32_t* r, uint32_t addr) {
    asm volatile("ldmatrix.sync.aligned.m8n8.x4.shared.b16 {%0,%1,%2,%3}, [%4];"
                 : "=r"(r[0]), "=r"(r[1]), "=r"(r[2]), "=r"(r[3]) : "r"(addr));
}
__device__ __forceinline__ void ldsm2(uint32_t* r, uint32_t addr) {
    asm volatile("ldmatrix.sync.aligned.m8n8.x2.shared.b16 {%0,%1}, [%2];"
                 : "=r"(r[0]), "=r"(r[1]) : "r"(addr));
}
__device__ __forceinline__ void mma16816(float* c, const uint32_t* a, const uint32_t* b) {
    asm volatile("mma.sync.aligned.m16n8k16.row.col.f32.f16.f16.f32 "
                 "{%0,%1,%2,%3}, {%4,%5,%6,%7}, {%8,%9}, {%0,%1,%2,%3};"
                 : "+f"(c[0]), "+f"(c[1]), "+f"(c[2]), "+f"(c[3])
                 : "r"(a[0]), "r"(a[1]), "r"(a[2]), "r"(a[3]), "r"(b[0]), "r"(b[1]));
}
__device__ __forceinline__ float gelu_fast(float x) {
    float u = 0.7978845608028654f * fmaf(0.044715f * x, x * x, x);
    float e, rc;
    asm("ex2.approx.f32 %0, %1;" : "=f"(e) : "f"(u * 2.8853900817779268f));
    asm("rcp.approx.f32 %0, %1;" : "=f"(rc) : "f"(e + 1.0f));
    return x * (1.0f - rc);
}

// ---------- prep: transpose W, round to fp16 ----------
__global__ void prep_w_kernel(const float* __restrict__ w0, const float* __restrict__ w1,
                              const float* __restrict__ w2, const float* __restrict__ w3) {
    int l = blockIdx.y, k = blockIdx.x, n = threadIdx.x;
    const float* w = (l == 0) ? w0 : (l == 1) ? w1 : (l == 2) ? w2 : w3;
    int kd = (l == 0) ? IN0 : MLPW;
    float v = (k < kd) ? w[k * MLPW + n] : 0.0f;
    g_wh[((size_t)l * 256 + n) * 256 + k] = __float2half_rn(v);
}

__global__ void film_kernel(const float* __restrict__ ctx,
                            const float* __restrict__ wf,
                            const float* __restrict__ bf) {
    int b = blockIdx.x, j = threadIdx.x;
    float acc = bf[j];
    const float* c = ctx + b * DM;
#pragma unroll 4
    for (int k = 0; k < DM; k++)
        acc = fmaf(__ldg(&c[k]), __ldg(&wf[k * 2 * MLPW + j]), acc);
    if (j < MLPW) g_gamma1[b * MLPW + j] = acc + 1.0f;
    else          g_beta[b * MLPW + (j - MLPW)] = acc;
}

// load W chunk (K=32 slice) for (layer l, local chunk c) into buffer buf (512 thr)
__device__ __forceinline__ void load_chunk(uint32_t base, int buf, int l, int c, int tid) {
    int row  = tid >> 1;
    int part = tid & 1;          // 32B half of the 64B row
    uint32_t d = base + WB0 + buf * WBUF + row * 80 + part * 32;
    const __half* s = g_wh + ((size_t)l * 256 + row) * 256 + c * 32 + part * 16;
    cp16(d, s);
    cp16(d + 16, s + 8);
}

// ---------- main kernel ----------
__global__ void __launch_bounds__(NTHR, 1)
decoder_kernel(const float* __restrict__ fgrid, const float* __restrict__ coords,
               const float* __restrict__ b0p, const float* __restrict__ b1p,
               const float* __restrict__ b2p, const float* __restrict__ b3p,
               const float* __restrict__ wo, const float* __restrict__ bo,
               float* __restrict__ out) {
    extern __shared__ char smc[];
    const uint32_t base = smem_u32(smc);
    const int tid  = threadIdx.x;
    const int w    = tid >> 5, lane = tid & 31;
    const int b    = blockIdx.y;
    const int n0g  = blockIdx.x * MT;
    const int m0   = (w & 1) * 64;           // warp M offset
    const int nw0  = (w >> 1) * 32;          // warp N offset (16 warps: 2x8)

    // lane-fixed ldmatrix offsets
    const int lg   = lane >> 3, lr = lane & 7;
    const int aRow = lr + ((lg & 1) << 3);
    const int aKh  = (lg >> 1) << 3;
    const int bN   = lr + ((lg >> 1) << 3);
    const int bKh  = (lg & 1) << 3;
    const uint32_t aOffH = base + A_HI + (uint32_t)(m0 + aRow) * ASTR + aKh * 2;
    const uint32_t bOff  = (uint32_t)(nw0 + bN) * 80 + bKh * 2;

    // prefetch first two W chunks of layer 0
    load_chunk(base, 0, 0, 0, tid); CP_COMMIT();
    load_chunk(base, 1, 0, 1, tid); CP_COMMIT();

    // stage params
    float* shg   = (float*)(smc + SM_G);
    float* shb   = (float*)(smc + SM_BETA);
    float* sbias = (float*)(smc + SM_BIAS);
    if (tid < 256) {
        shg[tid] = g_gamma1[b * MLPW + tid];
        shb[tid] = g_beta[b * MLPW + tid];
        sbias[tid]       = __ldg(&b0p[tid]);
        sbias[256 + tid] = __ldg(&b1p[tid]);
        sbias[512 + tid] = __ldg(&b2p[tid]);
        sbias[768 + tid] = __ldg(&b3p[tid]);
    }
    // stage w_out as fp16, padded to 8 n-rows x 256 k (n>=3 rows zero)
    {
#pragma unroll
        for (int e = 0; e < 4; e++) {
            int u = tid * 4 + e;          // 0..2047
            int n = u >> 8, k = u & 255;
            float v = (n < 3) ? __ldg(&wo[k * 3 + n]) : 0.0f;
            *(__half*)(smc + SM_WO + n * 528 + k * 2) = __float2half_rn(v);
        }
    }

    // ---------- phase A: enc + bilinear sample (vectorized, 4 thr/point) ----------
    {
        int p = tid >> 2, sub = tid & 3;
        int n = n0g + p;
        float cy = __ldg(&coords[2 * n]), cx = __ldg(&coords[2 * n + 1]);
        float py = fminf(fmaxf((cy + 1.0f) * 31.5f, 0.0f), 63.0f);
        float px = fminf(fmaxf((cx + 1.0f) * 31.5f, 0.0f), 63.0f);
        int y0i = min((int)py, 62), x0i = min((int)px, 62);
        float fy = py - (float)y0i, fx = px - (float)x0i;
        float w00 = (1.f - fy) * (1.f - fx), w01 = (1.f - fy) * fx;
        float w10 = fy * (1.f - fx), w11 = fy * fx;
        const float* gb = fgrid + (((size_t)b * 64 + y0i) * 64 + x0i) * DM;
        char* hb = smc + A_HI + p * ASTR;
#define PUT(j, v) do { *(__half*)(hb + 2*(j)) = __float2half_rn(v); } while(0)
        {
            int cs = sub * 32;
            const float4* q00 = (const float4*)gb + (cs >> 2);
            const float4* q01 = (const float4*)(gb + DM) + (cs >> 2);
            const float4* q10 = (const float4*)(gb + 8192) + (cs >> 2);
            const float4* q11 = (const float4*)(gb + 8192 + DM) + (cs >> 2);
#pragma unroll
            for (int q = 0; q < 8; q++) {
                float4 A = __ldg(q00 + q), B = __ldg(q01 + q);
                float4 C = __ldg(q10 + q), D = __ldg(q11 + q);
                int j0 = 42 + cs + 4 * q;
                PUT(j0 + 0, w00*A.x + w01*B.x + w10*C.x + w11*D.x);
                PUT(j0 + 1, w00*A.y + w01*B.y + w10*C.y + w11*D.y);
                PUT(j0 + 2, w00*A.z + w01*B.z + w10*C.z + w11*D.z);
                PUT(j0 + 3, w00*A.w + w01*B.w + w10*C.w + w11*D.w);
            }
        }
        if (sub == 0) {
            PUT(0, cy); PUT(1, cx);
            float sy, cyv, sx, cxv;
            sincosf(PI_F * cy, &sy, &cyv);
            sincosf(PI_F * cx, &sx, &cxv);
#pragma unroll
            for (int i = 0; i < NFREQ; i++) {
                PUT(2 + 4*i + 0, sy);  PUT(2 + 4*i + 1, sx);
                PUT(2 + 4*i + 2, cyv); PUT(2 + 4*i + 3, cxv);
                float ns = 2.f * sy * cyv, nc = 1.f - 2.f * sy * sy;
                sy = ns; cyv = nc;
                ns = 2.f * sx * cxv; nc = 1.f - 2.f * sx * sx;
                sx = ns; cxv = nc;
            }
        } else if (sub == 3) {
            // zero pad cols 170..191 (bytes 340..384, 4B-aligned)
#pragma unroll
            for (int q = 0; q < 11; q++)
                *(uint32_t*)(hb + 340 + 4*q) = 0u;
        }
#undef PUT
    }
    __syncthreads();

    // ---------- mainloop: 30 K=32 chunks over 4 layers, single pass ----------
    float acc[4][4][4];
#pragma unroll
    for (int i = 0; i < 4; i++)
#pragma unroll
        for (int j = 0; j < 4; j++)
#pragma unroll
            for (int r = 0; r < 4; r++) acc[i][j][r] = 0.0f;

    int layer = 0, cloc = 0, nch = 6;
#pragma unroll 1
    for (int g = 0; g < 30; g++) {
        cp_wait<1>();
        __syncthreads();
        // prefetch chunk g+2
        {
            int j = g + 2;
            if (j < 30) {
                int ln = (j < 6) ? 0 : (j - 6) / 8 + 1;
                int cn = (ln == 0) ? j : (j - 6) & 7;
                load_chunk(base, j % 3, ln, cn, tid);
            }
            CP_COMMIT();
        }
        // MMAs for chunk g (K=32: two k-subtiles of 16)
        {
            const uint32_t wb = base + WB0 + (uint32_t)(g % 3) * WBUF;
            const uint32_t k2 = (uint32_t)cloc * 64;
            uint32_t af[4][4], bfr[2][4];
#pragma unroll
            for (int ks = 0; ks < 2; ks++) {
                const uint32_t kb = k2 + (uint32_t)ks * 32;
#pragma unroll
                for (int j2 = 0; j2 < 2; j2++)
                    ldsm4(bfr[j2], wb + bOff + (uint32_t)ks * 32 + j2 * 1280);
#pragma unroll
                for (int i = 0; i < 4; i++) ldsm4(af[i], aOffH + i * (16 * ASTR) + kb);
#pragma unroll
                for (int i = 0; i < 4; i++)
#pragma unroll
                    for (int j = 0; j < 4; j++)
                        mma16816(acc[i][j], af[i], &bfr[j >> 1][(j & 1) * 2]);
            }
        }
        cloc++;
        if (cloc == nch) {
            // ---------- layer epilogue ----------
            const float* bl = sbias + layer * 256;
            const int cb = nw0 + 2 * (lane & 3);
            const int rb = m0 + (lane >> 2);
            // 1) gelu in place (before barrier: overlaps warp arrival skew)
#pragma unroll
            for (int j = 0; j < 4; j++) {
                int col = cb + 8 * j;
                float bi0 = bl[col], bi1 = bl[col + 1];
                float gg0 = shg[col], gg1 = shg[col + 1];
                float be0 = shb[col], be1 = shb[col + 1];
#pragma unroll
                for (int i = 0; i < 4; i++) {
                    acc[i][j][0] = gelu_fast(fmaf(acc[i][j][0] + bi0, gg0, be0));
                    acc[i][j][1] = gelu_fast(fmaf(acc[i][j][1] + bi1, gg1, be1));
                    acc[i][j][2] = gelu_fast(fmaf(acc[i][j][2] + bi0, gg0, be0));
                    acc[i][j][3] = gelu_fast(fmaf(acc[i][j][3] + bi1, gg1, be1));
                }
            }
            // 2) barrier: all warps done reading A for this layer
            __syncthreads();
            // 3) store to A hi plane, reset acc
#pragma unroll
            for (int j = 0; j < 4; j++) {
                int col = cb + 8 * j;
#pragma unroll
                for (int i = 0; i < 4; i++) {
                    int row = rb + 16 * i;
                    __half2 h0 = __floats2half2_rn(acc[i][j][0], acc[i][j][1]);
                    __half2 h1 = __floats2half2_rn(acc[i][j][2], acc[i][j][3]);
                    acc[i][j][0] = 0.0f; acc[i][j][1] = 0.0f;
                    acc[i][j][2] = 0.0f; acc[i][j][3] = 0.0f;
                    uint32_t o0 = (uint32_t)row * ASTR + (uint32_t)col * 2;
                    *(uint32_t*)(smc + A_HI + o0) = *(uint32_t*)&h0;
                    *(uint32_t*)(smc + A_HI + o0 + 8 * ASTR) = *(uint32_t*)&h1;
                }
            }
            layer++; cloc = 0; nch = 8;
        }
    }
    __syncthreads();

    // ---------- head: 128x8x256 fp16 MMA (warps 0-7, 16 rows each) ----------
    if (w < 8) {
        float hc[4] = {0.0f, 0.0f, 0.0f, 0.0f};
        const uint32_t aaddr = base + A_HI + (uint32_t)(w * 16 + aRow) * ASTR + aKh * 2;
        const uint32_t baddr = base + SM_WO + (uint32_t)(lane & 7) * 528
                               + ((uint32_t)((lane >> 3) & 1)) * 16;
#pragma unroll
        for (int ks = 0; ks < 16; ks++) {
            uint32_t af[4], bf2[2];
            ldsm4(af, aaddr + ks * 32);
            ldsm2(bf2, baddr + ks * 32);
            mma16816(hc, af, bf2);
        }
        int row = w * 16 + (lane >> 2);
        int col = (lane & 3) * 2;
        if (col < 3) {
            size_t ob = (size_t)b * NPTS + n0g;
            float bc0 = __ldg(&bo[col]);
            out[(ob + row) * 3 + col]     = tanhf(hc[0] + bc0);
            out[(ob + row + 8) * 3 + col] = tanhf(hc[2] + bc0);
            if (col + 1 < 3) {
                float bc1 = __ldg(&bo[col + 1]);
                out[(ob + row) * 3 + col + 1]     = tanhf(hc[1] + bc1);
                out[(ob + row + 8) * 3 + col + 1] = tanhf(hc[3] + bc1);
            }
        }
    }
}

extern "C" void kernel_launch(void* const* d_in, const int* in_sizes, int n_in,
                              void* d_out, int out_size) {
    const float* fgrid  = (const float*)d_in[0];
    const float* ctx    = (const float*)d_in[1];
    const float* coords = (const float*)d_in[2];
    const float* w0 = (const float*)d_in[3];
    const float* b0 = (const float*)d_in[4];
    const float* w1 = (const float*)d_in[5];
    const float* b1 = (const float*)d_in[6];
    const float* w2 = (const float*)d_in[7];
    const float* b2 = (const float*)d_in[8];
    const float* w3 = (const float*)d_in[9];
    const float* b3 = (const float*)d_in[10];
    const float* wf = (const float*)d_in[11];
    const float* bf = (const float*)d_in[12];
    const float* wo = (const float*)d_in[13];
    const float* bo = (const float*)d_in[14];
    float* out = (float*)d_out;

    cudaFuncSetAttribute(decoder_kernel,
                         cudaFuncAttributeMaxDynamicSharedMemorySize, SMEM_BYTES);

    dim3 pgrid(256, 4);
    prep_w_kernel<<<pgrid, 256>>>(w0, w1, w2, w3);
    film_kernel<<<BATCH, 2 * MLPW>>>(ctx, wf, bf);
    dim3 grid(NPTS / MT, BATCH);
    decoder_kernel<<<grid, NTHR, SMEM_BYTES>>>(fgrid, coords, b0, b1, b2, b3,
                                               wo, bo, out);
}

// round 13
// speedup vs baseline: 2.6216x; 1.1492x over previous
#include <cuda_runtime.h>
#include <cuda_fp16.h>
#include <cstdint>
#include <math.h>

#define NPTS   65536
#define BATCH  4
#define DM     128
#define MLPW   256
#define NFREQ  10
#define IN0    170
#define MT     128
#define PI_F   3.14159265358979323846f

// A smem: 128 rows x 264 fp16 (stride 528B), hi plane only
#define ASTR   528
#define A_HI   0
// W buffers: 3 x (256 rows x 144B)  (K=64 fp16 = 128B data + 16B pad)
#define WB0    67584
#define WBUF   36864
// params
#define SM_G    178176
#define SM_BETA 179200
#define SM_BIAS 180224
#define SM_WO   184320      // w_out fp16, 8 n-rows x 256 k, stride 528B
#define SMEM_BYTES 188544

#define NTHR   512

__device__ __align__(128) __half g_wh[4*256*256];
__device__ float g_gamma1[BATCH*MLPW];
__device__ float g_beta[BATCH*MLPW];

__device__ __forceinline__ uint32_t smem_u32(const void* p) {
    uint32_t a;
    asm("{ .reg .u64 t; cvta.to.shared.u64 t, %1; cvt.u32.u64 %0, t; }" : "=r"(a) : "l"(p));
    return a;
}
__device__ __forceinline__ void cp16(uint32_t dst, const void* src) {
    asm volatile("cp.async.cg.shared.global [%0], [%1], 16;" :: "r"(dst), "l"(src));
}
#define CP_COMMIT() asm volatile("cp.async.commit_group;" ::: "memory")
template <int N> __device__ __forceinline__ void cp_wait() {
    asm volatile("cp.async.wait_group %0;" :: "n"(N) : "memory");
}
__device__ __forceinline__ void ldsm4(uint32_t* r, uint32_t addr) {
    asm volatile("ldmatrix.sync.aligned.m8n8.x4.shared.b16 {%0,%1,%2,%3}, [%4];"
                 : "=r"(r[0]), "=r"(r[1]), "=r"(r[2]), "=r"(r[3]) : "r"(addr));
}
__device__ __forceinline__ void ldsm2(uint32_t* r, uint32_t addr) {
    asm volatile("ldmatrix.sync.aligned.m8n8.x2.shared.b16 {%0,%1}, [%2];"
                 : "=r"(r[0]), "=r"(r[1]) : "r"(addr));
}
__device__ __forceinline__ void mma16816(float* c, const uint32_t* a, const uint32_t* b) {
    asm volatile("mma.sync.aligned.m16n8k16.row.col.f32.f16.f16.f32 "
                 "{%0,%1,%2,%3}, {%4,%5,%6,%7}, {%8,%9}, {%0,%1,%2,%3};"
                 : "+f"(c[0]), "+f"(c[1]), "+f"(c[2]), "+f"(c[3])
                 : "r"(a[0]), "r"(a[1]), "r"(a[2]), "r"(a[3]), "r"(b[0]), "r"(b[1]));
}
__device__ __forceinline__ float gelu_fast(float x) {
    float u = 0.7978845608028654f * fmaf(0.044715f * x, x * x, x);
    float e, rc;
    asm("ex2.approx.f32 %0, %1;" : "=f"(e) : "f"(u * 2.8853900817779268f));
    asm("rcp.approx.f32 %0, %1;" : "=f"(rc) : "f"(e + 1.0f));
    return x * (1.0f - rc);
}

// ---------- prep: transpose W, round to fp16 ----------
__global__ void prep_w_kernel(const float* __restrict__ w0, const float* __restrict__ w1,
                              const float* __restrict__ w2, const float* __restrict__ w3) {
    int l = blockIdx.y, k = blockIdx.x, n = threadIdx.x;
    const float* w = (l == 0) ? w0 : (l == 1) ? w1 : (l == 2) ? w2 : w3;
    int kd = (l == 0) ? IN0 : MLPW;
    float v = (k < kd) ? w[k * MLPW + n] : 0.0f;
    g_wh[((size_t)l * 256 + n) * 256 + k] = __float2half_rn(v);
}

__global__ void film_kernel(const float* __restrict__ ctx,
                            const float* __restrict__ wf,
                            const float* __restrict__ bf) {
    int b = blockIdx.x, j = threadIdx.x;
    float acc = bf[j];
    const float* c = ctx + b * DM;
#pragma unroll 4
    for (int k = 0; k < DM; k++)
        acc = fmaf(__ldg(&c[k]), __ldg(&wf[k * 2 * MLPW + j]), acc);
    if (j < MLPW) g_gamma1[b * MLPW + j] = acc + 1.0f;
    else          g_beta[b * MLPW + (j - MLPW)] = acc;
}

// load W chunk (K=64 slice) for (layer l, local chunk c) into buffer buf (512 thr)
__device__ __forceinline__ void load_chunk(uint32_t base, int buf, int l, int c, int tid) {
    int row  = tid >> 1;
    int part = tid & 1;          // 64B half of the 128B row
    uint32_t d = base + WB0 + buf * WBUF + row * 144 + part * 64;
    const __half* s = g_wh + ((size_t)l * 256 + row) * 256 + c * 64 + part * 32;
    cp16(d, s);
    cp16(d + 16, s + 8);
    cp16(d + 32, s + 16);
    cp16(d + 48, s + 24);
}

// ---------- main kernel ----------
__global__ void __launch_bounds__(NTHR, 1)
decoder_kernel(const float* __restrict__ fgrid, const float* __restrict__ coords,
               const float* __restrict__ b0p, const float* __restrict__ b1p,
               const float* __restrict__ b2p, const float* __restrict__ b3p,
               const float* __restrict__ wo, const float* __restrict__ bo,
               float* __restrict__ out) {
    extern __shared__ char smc[];
    const uint32_t base = smem_u32(smc);
    const int tid  = threadIdx.x;
    const int w    = tid >> 5, lane = tid & 31;
    const int b    = blockIdx.y;
    const int n0g  = blockIdx.x * MT;
    const int m0   = (w & 1) * 64;           // warp M offset
    const int nw0  = (w >> 1) * 32;          // warp N offset (16 warps: 2x8)

    // lane-fixed ldmatrix offsets
    const int lg   = lane >> 3, lr = lane & 7;
    const int aRow = lr + ((lg & 1) << 3);
    const int aKh  = (lg >> 1) << 3;
    const int bN   = lr + ((lg >> 1) << 3);
    const int bKh  = (lg & 1) << 3;
    const uint32_t aOffH = base + A_HI + (uint32_t)(m0 + aRow) * ASTR + aKh * 2;
    const uint32_t bOff  = (uint32_t)(nw0 + bN) * 144 + bKh * 2;

    // prefetch first two W chunks of layer 0
    load_chunk(base, 0, 0, 0, tid); CP_COMMIT();
    load_chunk(base, 1, 0, 1, tid); CP_COMMIT();

    // stage params
    float* shg   = (float*)(smc + SM_G);
    float* shb   = (float*)(smc + SM_BETA);
    float* sbias = (float*)(smc + SM_BIAS);
    if (tid < 256) {
        shg[tid] = g_gamma1[b * MLPW + tid];
        shb[tid] = g_beta[b * MLPW + tid];
        sbias[tid]       = __ldg(&b0p[tid]);
        sbias[256 + tid] = __ldg(&b1p[tid]);
        sbias[512 + tid] = __ldg(&b2p[tid]);
        sbias[768 + tid] = __ldg(&b3p[tid]);
    }
    // stage w_out as fp16, padded to 8 n-rows x 256 k (n>=3 rows zero)
    {
#pragma unroll
        for (int e = 0; e < 4; e++) {
            int u = tid * 4 + e;          // 0..2047
            int n = u >> 8, k = u & 255;
            float v = (n < 3) ? __ldg(&wo[k * 3 + n]) : 0.0f;
            *(__half*)(smc + SM_WO + n * 528 + k * 2) = __float2half_rn(v);
        }
    }

    // ---------- phase A: enc + bilinear sample (4 thr/point, interleaved f4) ----------
    {
        int p = tid >> 2, sub = tid & 3;
        int n = n0g + p;
        float cy = __ldg(&coords[2 * n]), cx = __ldg(&coords[2 * n + 1]);
        float py = fminf(fmaxf((cy + 1.0f) * 31.5f, 0.0f), 63.0f);
        float px = fminf(fmaxf((cx + 1.0f) * 31.5f, 0.0f), 63.0f);
        int y0i = min((int)py, 62), x0i = min((int)px, 62);
        float fy = py - (float)y0i, fx = px - (float)x0i;
        float w00 = (1.f - fy) * (1.f - fx), w01 = (1.f - fy) * fx;
        float w10 = fy * (1.f - fx), w11 = fy * fx;
        const float* gb = fgrid + (((size_t)b * 64 + y0i) * 64 + x0i) * DM;
        char* hb = smc + A_HI + p * ASTR;
        const float4* q00 = (const float4*)gb;
        const float4* q01 = (const float4*)(gb + DM);
        const float4* q10 = (const float4*)(gb + 8192);
        const float4* q11 = (const float4*)(gb + 8192 + DM);
        // interleaved: thread sub handles float4 indices q*4+sub  (lanes of a
        // point read 64 consecutive bytes per instruction -> ~1 line/point)
#pragma unroll
        for (int q = 0; q < 8; q++) {
            int f = q * 4 + sub;
            float4 A = __ldg(q00 + f), B = __ldg(q01 + f);
            float4 C = __ldg(q10 + f), D = __ldg(q11 + f);
            float v0 = w00*A.x + w01*B.x + w10*C.x + w11*D.x;
            float v1 = w00*A.y + w01*B.y + w10*C.y + w11*D.y;
            float v2 = w00*A.z + w01*B.z + w10*C.z + w11*D.z;
            float v3 = w00*A.w + w01*B.w + w10*C.w + w11*D.w;
            __half2 p0 = __floats2half2_rn(v0, v1);
            __half2 p1 = __floats2half2_rn(v2, v3);
            // channels 42+4f .. 42+4f+3 -> bytes 84+8f (4B aligned)
            *(uint32_t*)(hb + 84 + 8 * f)     = *(uint32_t*)&p0;
            *(uint32_t*)(hb + 84 + 8 * f + 4) = *(uint32_t*)&p1;
        }
#define PUT(j, v) do { *(__half*)(hb + 2*(j)) = __float2half_rn(v); } while(0)
        if (sub == 0) {
            PUT(0, cy); PUT(1, cx);
            float sy, cyv, sx, cxv;
            sincosf(PI_F * cy, &sy, &cyv);
            sincosf(PI_F * cx, &sx, &cxv);
#pragma unroll
            for (int i = 0; i < NFREQ; i++) {
                PUT(2 + 4*i + 0, sy);  PUT(2 + 4*i + 1, sx);
                PUT(2 + 4*i + 2, cyv); PUT(2 + 4*i + 3, cxv);
                float ns = 2.f * sy * cyv, nc = 1.f - 2.f * sy * sy;
                sy = ns; cyv = nc;
                ns = 2.f * sx * cxv; nc = 1.f - 2.f * sx * sx;
                sx = ns; cxv = nc;
            }
        } else if (sub == 3) {
            // zero pad cols 170..191 (bytes 340..384, 4B-aligned)
#pragma unroll
            for (int q2 = 0; q2 < 11; q2++)
                *(uint32_t*)(hb + 340 + 4*q2) = 0u;
        }
#undef PUT
    }
    __syncthreads();

    // ---------- mainloop: 15 K=64 chunks over 4 layers, single pass ----------
    float acc[4][4][4];
#pragma unroll
    for (int i = 0; i < 4; i++)
#pragma unroll
        for (int j = 0; j < 4; j++)
#pragma unroll
            for (int r = 0; r < 4; r++) acc[i][j][r] = 0.0f;

    int layer = 0, cloc = 0, nch = 3;
#pragma unroll 1
    for (int g = 0; g < 15; g++) {
        cp_wait<1>();
        __syncthreads();
        // prefetch chunk g+2
        {
            int j = g + 2;
            if (j < 15) {
                int ln = (j < 3) ? 0 : (j - 3) / 4 + 1;
                int cn = (ln == 0) ? j : (j - 3) & 3;
                load_chunk(base, j % 3, ln, cn, tid);
            }
            CP_COMMIT();
        }
        // MMAs for chunk g (K=64: four k-subtiles of 16)
        {
            const uint32_t wb = base + WB0 + (uint32_t)(g % 3) * WBUF;
            const uint32_t k2 = (uint32_t)cloc * 128;
            uint32_t af[4][4], bfr[2][4];
#pragma unroll
            for (int ks = 0; ks < 4; ks++) {
                const uint32_t kb = k2 + (uint32_t)ks * 32;
#pragma unroll
                for (int j2 = 0; j2 < 2; j2++)
                    ldsm4(bfr[j2], wb + bOff + (uint32_t)ks * 32 + j2 * 2304);
#pragma unroll
                for (int i = 0; i < 4; i++) ldsm4(af[i], aOffH + i * (16 * ASTR) + kb);
#pragma unroll
                for (int i = 0; i < 4; i++)
#pragma unroll
                    for (int j = 0; j < 4; j++)
                        mma16816(acc[i][j], af[i], &bfr[j >> 1][(j & 1) * 2]);
            }
        }
        cloc++;
        if (cloc == nch) {
            // ---------- layer epilogue ----------
            const float* bl = sbias + layer * 256;
            const int cb = nw0 + 2 * (lane & 3);
            const int rb = m0 + (lane >> 2);
            // 1) gelu in place (before barrier: overlaps warp arrival skew)
#pragma unroll
            for (int j = 0; j < 4; j++) {
                int col = cb + 8 * j;
                float bi0 = bl[col], bi1 = bl[col + 1];
                float gg0 = shg[col], gg1 = shg[col + 1];
                float be0 = shb[col], be1 = shb[col + 1];
#pragma unroll
                for (int i = 0; i < 4; i++) {
                    acc[i][j][0] = gelu_fast(fmaf(acc[i][j][0] + bi0, gg0, be0));
                    acc[i][j][1] = gelu_fast(fmaf(acc[i][j][1] + bi1, gg1, be1));
                    acc[i][j][2] = gelu_fast(fmaf(acc[i][j][2] + bi0, gg0, be0));
                    acc[i][j][3] = gelu_fast(fmaf(acc[i][j][3] + bi1, gg1, be1));
                }
            }
            // 2) barrier: all warps done reading A for this layer
            __syncthreads();
            // 3) store to A hi plane, reset acc
#pragma unroll
            for (int j = 0; j < 4; j++) {
                int col = cb + 8 * j;
#pragma unroll
                for (int i = 0; i < 4; i++) {
                    int row = rb + 16 * i;
                    __half2 h0 = __floats2half2_rn(acc[i][j][0], acc[i][j][1]);
                    __half2 h1 = __floats2half2_rn(acc[i][j][2], acc[i][j][3]);
                    acc[i][j][0] = 0.0f; acc[i][j][1] = 0.0f;
                    acc[i][j][2] = 0.0f; acc[i][j][3] = 0.0f;
                    uint32_t o0 = (uint32_t)row * ASTR + (uint32_t)col * 2;
                    *(uint32_t*)(smc + A_HI + o0) = *(uint32_t*)&h0;
                    *(uint32_t*)(smc + A_HI + o0 + 8 * ASTR) = *(uint32_t*)&h1;
                }
            }
            layer++; cloc = 0; nch = 4;
        }
    }
    __syncthreads();

    // ---------- head: 128x8x256 fp16 MMA (warps 0-7, 16 rows each) ----------
    if (w < 8) {
        float hc[4] = {0.0f, 0.0f, 0.0f, 0.0f};
        const uint32_t aaddr = base + A_HI + (uint32_t)(w * 16 + aRow) * ASTR + aKh * 2;
        const uint32_t baddr = base + SM_WO + (uint32_t)(lane & 7) * 528
                               + ((uint32_t)((lane >> 3) & 1)) * 16;
#pragma unroll
        for (int ks = 0; ks < 16; ks++) {
            uint32_t af[4], bf2[2];
            ldsm4(af, aaddr + ks * 32);
            ldsm2(bf2, baddr + ks * 32);
            mma16816(hc, af, bf2);
        }
        int row = w * 16 + (lane >> 2);
        int col = (lane & 3) * 2;
        if (col < 3) {
            size_t ob = (size_t)b * NPTS + n0g;
            float bc0 = __ldg(&bo[col]);
            out[(ob + row) * 3 + col]     = tanhf(hc[0] + bc0);
            out[(ob + row + 8) * 3 + col] = tanhf(hc[2] + bc0);
            if (col + 1 < 3) {
                float bc1 = __ldg(&bo[col + 1]);
                out[(ob + row) * 3 + col + 1]     = tanhf(hc[1] + bc1);
                out[(ob + row + 8) * 3 + col + 1] = tanhf(hc[3] + bc1);
            }
        }
    }
}

extern "C" void kernel_launch(void* const* d_in, const int* in_sizes, int n_in,
                              void* d_out, int out_size) {
    const float* fgrid  = (const float*)d_in[0];
    const float* ctx    = (const float*)d_in[1];
    const float* coords = (const float*)d_in[2];
    const float* w0 = (const float*)d_in[3];
    const float* b0 = (const float*)d_in[4];
    const float* w1 = (const float*)d_in[5];
    const float* b1 = (const float*)d_in[6];
    const float* w2 = (const float*)d_in[7];
    const float* b2 = (const float*)d_in[8];
    const float* w3 = (const float*)d_in[9];
    const float* b3 = (const float*)d_in[10];
    const float* wf = (const float*)d_in[11];
    const float* bf = (const float*)d_in[12];
    const float* wo = (const float*)d_in[13];
    const float* bo = (const float*)d_in[14];
    float* out = (float*)d_out;

    cudaFuncSetAttribute(decoder_kernel,
                         cudaFuncAttributeMaxDynamicSharedMemorySize, SMEM_BYTES);

    dim3 pgrid(256, 4);
    prep_w_kernel<<<pgrid, 256>>>(w0, w1, w2, w3);
    film_kernel<<<BATCH, 2 * MLPW>>>(ctx, wf, bf);
    dim3 grid(NPTS / MT, BATCH);
    decoder_kernel<<<grid, NTHR, SMEM_BYTES>>>(fgrid, coords, b0, b1, b2, b3,
                                               wo, bo, out);
}